// round 6
// baseline (speedup 1.0000x reference)
#include <cuda_runtime.h>
#include <cuda_fp16.h>
#include <math.h>
#include <stdint.h>

// RoutingLayer via mma.sync m16n8k16 fp16 (portable PTX for sm_103 target).
// out[B,64] = scatter(softmax(top2(x@w_gate + noise*(softplus(x@w_noise)+0.01))))
// B=32768, D=2048, E=64. Fused GEMM N=128 (0..63 gate, 64..127 noise).
// FP16x2 split: x=h0+h1, (256*w)=h0+h1; h0h0 + h0h1 + h1h0, scaled by 2^-8.
// R6: term-major MMA interleave (dep distance 8) + N-split warps (32Mx64N)
//     to halve B smem re-reads; epilogue staged once through smem.

#define KDIM 2048
#define EDIM 64
#define BM   128
#define BKC  32
#define NCHUNK (KDIM / BKC)   // 64
#define TPB  256
#define CP   132              // C staging pitch (floats)

// smem 16B units per buffer: A [0,1280): (s*128+row)*5+tig ; B [1280,2304)
#define BUF_U 2304
#define SMEM_BYTES (2 * BUF_U * 16)   // 73728 >= 128*CP*4 = 67584 for staging

// pre-split weights: [k16 step s(128)][n(128)][tig(4)] uint4 = (b0_h0,b1_h0,b0_h1,b1_h1)
__device__ uint4 g_wb[128 * 128 * 4];   // 1 MB

__device__ __forceinline__ uint32_t pack2(__half lo, __half hi) {
    __half2 h = __halves2half2(lo, hi);
    return *(uint32_t*)&h;
}

__device__ __forceinline__ void mma16(float* c, uint32_t a0, uint32_t a1,
                                      uint32_t a2, uint32_t a3,
                                      uint32_t b0, uint32_t b1) {
    asm volatile(
        "mma.sync.aligned.m16n8k16.row.col.f32.f16.f16.f32 "
        "{%0,%1,%2,%3}, {%4,%5,%6,%7}, {%8,%9}, {%0,%1,%2,%3};"
        : "+f"(c[0]), "+f"(c[1]), "+f"(c[2]), "+f"(c[3])
        : "r"(a0), "r"(a1), "r"(a2), "r"(a3), "r"(b0), "r"(b1));
}

__device__ __forceinline__ uint32_t smem_u32(const void* p) {
    uint32_t a;
    asm("{ .reg .u64 t; cvta.to.shared.u64 t, %1; cvt.u32.u64 %0, t; }" : "=r"(a) : "l"(p));
    return a;
}
#define CP_ASYNC16(dst, src) \
    asm volatile("cp.async.cg.shared.global [%0], [%1], 16;" :: "r"(dst), "l"(src) : "memory")
#define CP_COMMIT() asm volatile("cp.async.commit_group;" ::: "memory")
#define CP_WAIT0()  asm volatile("cp.async.wait_group 0;" ::: "memory")

// ---- prep: split 256*w into fp16 (h0,h1), fragment-native B layout ----
__global__ void prep_w(const float* __restrict__ wg, const float* __restrict__ wn) {
    const int idx = blockIdx.x * blockDim.x + threadIdx.x;  // 0..65535
    const int tig = idx & 3;
    const int n   = (idx >> 2) & 127;
    const int s   = idx >> 9;            // k16 step 0..127
    const int kb  = s * 16;
    const int kk[4] = {kb + 2*tig, kb + 2*tig + 1, kb + 2*tig + 8, kb + 2*tig + 9};
    float v[4];
    #pragma unroll
    for (int j = 0; j < 4; j++)
        v[j] = 256.0f * ((n < 64) ? wg[kk[j] * 64 + n] : wn[kk[j] * 64 + (n - 64)]);
    __half h0[4], h1[4];
    #pragma unroll
    for (int j = 0; j < 4; j++) {
        h0[j] = __float2half_rn(v[j]);
        h1[j] = __float2half_rn(v[j] - __half2float(h0[j]));
    }
    uint4 w4;
    w4.x = pack2(h0[0], h0[1]);
    w4.y = pack2(h0[2], h0[3]);
    w4.z = pack2(h1[0], h1[1]);
    w4.w = pack2(h1[2], h1[3]);
    g_wb[(size_t)(s * 128 + n) * 4 + tig] = w4;
}

// ---- main ----
__global__ __launch_bounds__(TPB, 2)
void routing_mma(const float* __restrict__ x,
                 const float* __restrict__ nz,
                 float* __restrict__ out)
{
    extern __shared__ uint4 sm4[];
    const int tid = threadIdx.x;
    const int wid = tid >> 5;
    const int lane = tid & 31;
    const int gid = lane >> 2;
    const int tig = lane & 3;
    const int r0 = blockIdx.x * BM;
    const int mw  = (wid >> 1) * 32;      // warp rows [mw, mw+32)
    const int nw8 = (wid & 1) * 8;        // warp n-tiles [nw8, nw8+8) (n = nt*8)

    float c[2][8][4];
    #pragma unroll
    for (int mt = 0; mt < 2; mt++)
        #pragma unroll
        for (int nt = 0; nt < 8; nt++)
            #pragma unroll
            for (int j = 0; j < 4; j++) c[mt][nt][j] = 0.f;

    // producer mappings
    const int arow = tid & 127;
    const int as   = tid >> 7;
    const float* xp = x + (size_t)(r0 + arow) * KDIM + as * 16;
    const int aunit0 = (as * 128 + arow) * 5;

    const uint32_t sb = smem_u32(sm4);

    // ---- prologue: chunk 0 into buffer 0 ----
    {
        float v[16];
        #pragma unroll
        for (int q = 0; q < 4; q++)
            *(float4*)&v[4 * q] = *(const float4*)(xp + 4 * q);
        #pragma unroll
        for (int tg = 0; tg < 4; tg++) {
            const int i0 = 2*tg, i1 = 2*tg+1, i2 = 2*tg+8, i3 = 2*tg+9;
            __half a0 = __float2half_rn(v[i0]), a1 = __float2half_rn(v[i1]);
            __half a2 = __float2half_rn(v[i2]), a3 = __float2half_rn(v[i3]);
            uint4 w4;
            w4.x = pack2(a0, a1);
            w4.y = pack2(a2, a3);
            w4.z = pack2(__float2half_rn(v[i0] - __half2float(a0)),
                         __float2half_rn(v[i1] - __half2float(a1)));
            w4.w = pack2(__float2half_rn(v[i2] - __half2float(a2)),
                         __float2half_rn(v[i3] - __half2float(a3)));
            sm4[aunit0 + tg] = w4;
        }
        const uint4* src = g_wb + tid;
        #pragma unroll
        for (int j = 0; j < 4; j++) {
            uint32_t dst = sb + (uint32_t)(1280 + j * 256 + tid) * 16u;
            CP_ASYNC16(dst, src + j * 256);
        }
        CP_COMMIT();
        CP_WAIT0();
    }
    __syncthreads();

    int p = 0;
    for (int t = 0; t < NCHUNK; t++) {
        float v[16];
        const bool more = (t + 1 < NCHUNK);
        if (more) {
            #pragma unroll
            for (int q = 0; q < 4; q++)
                *(float4*)&v[4 * q] = *(const float4*)(xp + (t + 1) * BKC + 4 * q);
            const uint4* src = g_wb + (size_t)(t + 1) * 1024 + tid;
            const int qb = 1 - p;
            #pragma unroll
            for (int j = 0; j < 4; j++) {
                uint32_t dst = sb + (uint32_t)(qb * BUF_U + 1280 + j * 256 + tid) * 16u;
                CP_ASYNC16(dst, src + j * 256);
            }
            CP_COMMIT();
        }

        // ---- compute chunk t from buffer p (term-major, dep distance 8) ----
        {
            const uint4* buf = sm4 + p * BUF_U;
            #pragma unroll
            for (int s = 0; s < 2; s++) {
                uint4 A0  = buf[(s * 128 + mw + gid) * 5 + tig];
                uint4 A8  = buf[(s * 128 + mw + gid + 8) * 5 + tig];
                uint4 A16 = buf[(s * 128 + mw + gid + 16) * 5 + tig];
                uint4 A24 = buf[(s * 128 + mw + gid + 24) * 5 + tig];
                const uint4* bb = buf + 1280 + s * 512;
                #pragma unroll
                for (int ntb = 0; ntb < 2; ntb++) {
                    uint4 Bv[4];
                    #pragma unroll
                    for (int j = 0; j < 4; j++)
                        Bv[j] = bb[((nw8 + ntb * 4 + j) * 8 + gid) * 4 + tig];
                    // term h0a*h0b
                    #pragma unroll
                    for (int j = 0; j < 4; j++) {
                        mma16(c[0][ntb*4+j], A0.x, A8.x, A0.y, A8.y, Bv[j].x, Bv[j].y);
                        mma16(c[1][ntb*4+j], A16.x, A24.x, A16.y, A24.y, Bv[j].x, Bv[j].y);
                    }
                    // term h0a*h1b
                    #pragma unroll
                    for (int j = 0; j < 4; j++) {
                        mma16(c[0][ntb*4+j], A0.x, A8.x, A0.y, A8.y, Bv[j].z, Bv[j].w);
                        mma16(c[1][ntb*4+j], A16.x, A24.x, A16.y, A24.y, Bv[j].z, Bv[j].w);
                    }
                    // term h1a*h0b
                    #pragma unroll
                    for (int j = 0; j < 4; j++) {
                        mma16(c[0][ntb*4+j], A0.z, A8.z, A0.w, A8.w, Bv[j].x, Bv[j].y);
                        mma16(c[1][ntb*4+j], A16.z, A24.z, A16.w, A24.w, Bv[j].x, Bv[j].y);
                    }
                }
            }
        }

        if (more) {
            const int qb = 1 - p;
            #pragma unroll
            for (int tg = 0; tg < 4; tg++) {
                const int i0 = 2*tg, i1 = 2*tg+1, i2 = 2*tg+8, i3 = 2*tg+9;
                __half a0 = __float2half_rn(v[i0]), a1 = __float2half_rn(v[i1]);
                __half a2 = __float2half_rn(v[i2]), a3 = __float2half_rn(v[i3]);
                uint4 w4;
                w4.x = pack2(a0, a1);
                w4.y = pack2(a2, a3);
                w4.z = pack2(__float2half_rn(v[i0] - __half2float(a0)),
                             __float2half_rn(v[i1] - __half2float(a1)));
                w4.w = pack2(__float2half_rn(v[i2] - __half2float(a2)),
                             __float2half_rn(v[i3] - __half2float(a3)));
                sm4[qb * BUF_U + aunit0 + tg] = w4;
            }
            CP_WAIT0();
            __syncthreads();
            p = qb;
        }
    }

    // ---- stage C through smem (gate & noise cols live in different warps) ----
    const float S = 1.0f / 256.0f;
    __syncthreads();
    {
        float* Cs = (float*)sm4;
        #pragma unroll
        for (int mt = 0; mt < 2; mt++) {
            #pragma unroll
            for (int nt = 0; nt < 8; nt++) {
                const int m = mw + mt * 16 + gid;
                const int n = (nw8 + nt) * 8 + 2 * tig;
                *(float2*)(Cs + m * CP + n) =
                    make_float2(c[mt][nt][0] * S, c[mt][nt][1] * S);
                *(float2*)(Cs + (m + 8) * CP + n) =
                    make_float2(c[mt][nt][2] * S, c[mt][nt][3] * S);
            }
        }
    }
    __syncthreads();

    // ---- epilogue: one thread per row ----
    if (tid < BM) {
        const int r = tid;
        const int row = r0 + r;
        const float* Cs = (const float*)sm4;
        const float4* nzr = (const float4*)(nz + (size_t)row * EDIM);

        float v1 = -INFINITY, v2 = -INFINITY;
        int i1 = 0x7fffffff, i2 = 0x7fffffff;
        #pragma unroll 4
        for (int e4 = 0; e4 < 16; e4++) {
            float4 z = nzr[e4];
            const float zf[4] = {z.x, z.y, z.z, z.w};
            #pragma unroll
            for (int j = 0; j < 4; j++) {
                const int e = e4 * 4 + j;
                float g = Cs[r * CP + e];
                float s = Cs[r * CP + 64 + e];
                float sp = fmaxf(s, 0.f) + log1pf(expf(-fabsf(s)));
                float v = fmaf(zf[j], sp + 0.01f, g);
                if (v > v1)      { v2 = v1; i2 = i1; v1 = v; i1 = e; }
                else if (v > v2) { v2 = v; i2 = e; }
            }
        }

        float e2 = expf(v2 - v1);
        float denom = 1.f + e2;
        float g1 = 1.f / denom;
        float g2 = e2 / denom;

        float4* orow = (float4*)(out + (size_t)row * EDIM);
        #pragma unroll 4
        for (int e4 = 0; e4 < 16; e4++) {
            float o[4];
            #pragma unroll
            for (int j = 0; j < 4; j++) {
                const int e = e4 * 4 + j;
                o[j] = (e == i1) ? g1 : ((e == i2) ? g2 : 0.f);
            }
            orow[e4] = make_float4(o[0], o[1], o[2], o[3]);
        }
    }
}

extern "C" void kernel_launch(void* const* d_in, const int* in_sizes, int n_in,
                              void* d_out, int out_size)
{
    const float* x  = (const float*)d_in[0];   // [32768, 2048]
    const float* wg = (const float*)d_in[1];   // [2048, 64]
    const float* wn = (const float*)d_in[2];   // [2048, 64]
    const float* nz = (const float*)d_in[3];   // [32768, 64]
    float* out = (float*)d_out;                // [32768, 64]

    prep_w<<<256, 256>>>(wg, wn);

    cudaFuncSetAttribute(routing_mma, cudaFuncAttributeMaxDynamicSharedMemorySize,
                         SMEM_BYTES);
    const int B = in_sizes[0] / KDIM;          // 32768
    routing_mma<<<B / BM, TPB, SMEM_BYTES>>>(x, nz, out);
}

// round 7
// speedup vs baseline: 1.2880x; 1.2880x over previous
#include <cuda_runtime.h>
#include <cuda_fp16.h>
#include <math.h>
#include <stdint.h>

// RoutingLayer via mma.sync m16n8k16 fp16 (portable PTX for sm_103 target).
// out[B,64] = scatter(softmax(top2(x@w_gate + noise*(softplus(x@w_noise)+0.01))))
// B=32768, D=2048, E=64. Fused GEMM N=128 (0..63 gate, 64..127 noise).
// FP16x2 split: x=h0+h1, (256*w)=h0+h1; h0h0 + h0h1 + h1h0, scaled 2^-8.
// R7 (= R5 revert + fix): A rows are warp-private -> load A fragments DIRECTLY
// from gmem (float2 k-pairs, full 32B sectors), convert in registers. No A smem.
// Only B lives in smem (cp.async double buffer). Cuts ~1/3 of L1 wavefronts.

#define KDIM 2048
#define EDIM 64
#define BM   128
#define BKC  32
#define NCHUNK (KDIM / BKC)   // 64
#define TPB  256

// smem: B only. Per buffer 1024 16B-units: unit = s*512 + n*4 + tig
#define BUF_U 1024
#define SMEM_BYTES (2 * BUF_U * 16)   // 32768

// pre-split weights: [k16 step s(128)][n(128)][tig(4)] uint4 = (b0_h0,b1_h0,b0_h1,b1_h1)
__device__ uint4 g_wb[128 * 128 * 4];   // 1 MB

__device__ __forceinline__ uint32_t pack2(__half lo, __half hi) {
    __half2 h = __halves2half2(lo, hi);
    return *(uint32_t*)&h;
}

__device__ __forceinline__ void mma16(float* c, uint32_t a0, uint32_t a1,
                                      uint32_t a2, uint32_t a3,
                                      uint32_t b0, uint32_t b1) {
    asm volatile(
        "mma.sync.aligned.m16n8k16.row.col.f32.f16.f16.f32 "
        "{%0,%1,%2,%3}, {%4,%5,%6,%7}, {%8,%9}, {%0,%1,%2,%3};"
        : "+f"(c[0]), "+f"(c[1]), "+f"(c[2]), "+f"(c[3])
        : "r"(a0), "r"(a1), "r"(a2), "r"(a3), "r"(b0), "r"(b1));
}

__device__ __forceinline__ uint32_t smem_u32(const void* p) {
    uint32_t a;
    asm("{ .reg .u64 t; cvta.to.shared.u64 t, %1; cvt.u32.u64 %0, t; }" : "=r"(a) : "l"(p));
    return a;
}
#define CP_ASYNC16(dst, src) \
    asm volatile("cp.async.cg.shared.global [%0], [%1], 16;" :: "r"(dst), "l"(src) : "memory")
#define CP_COMMIT() asm volatile("cp.async.commit_group;" ::: "memory")
#define CP_WAIT0()  asm volatile("cp.async.wait_group 0;" ::: "memory")

// ---- prep: split 256*w into fp16 (h0,h1), fragment-native B layout ----
__global__ void prep_w(const float* __restrict__ wg, const float* __restrict__ wn) {
    const int idx = blockIdx.x * blockDim.x + threadIdx.x;  // 0..65535
    const int tig = idx & 3;
    const int n   = (idx >> 2) & 127;
    const int s   = idx >> 9;            // k16 step 0..127
    const int kb  = s * 16;
    const int kk[4] = {kb + 2*tig, kb + 2*tig + 1, kb + 2*tig + 8, kb + 2*tig + 9};
    float v[4];
    #pragma unroll
    for (int j = 0; j < 4; j++)
        v[j] = 256.0f * ((n < 64) ? wg[kk[j] * 64 + n] : wn[kk[j] * 64 + (n - 64)]);
    __half h0[4], h1[4];
    #pragma unroll
    for (int j = 0; j < 4; j++) {
        h0[j] = __float2half_rn(v[j]);
        h1[j] = __float2half_rn(v[j] - __half2float(h0[j]));
    }
    uint4 w4;
    w4.x = pack2(h0[0], h0[1]);
    w4.y = pack2(h0[2], h0[3]);
    w4.z = pack2(h1[0], h1[1]);
    w4.w = pack2(h1[2], h1[3]);
    g_wb[(size_t)(s * 128 + n) * 4 + tig] = w4;
}

// convert 4 float2 k-pairs (rows gid / gid+8) into hi/lo fragment regs for one s-half
__device__ __forceinline__ void cvt_frag(const float2* r, uint32_t* ah, uint32_t* al) {
    // r[0]=row0 pair0, r[1]=row8 pair0, r[2]=row0 pair1, r[3]=row8 pair1
    #pragma unroll
    for (int j = 0; j < 4; j++) {
        __half h0a = __float2half_rn(r[j].x);
        __half h0b = __float2half_rn(r[j].y);
        ah[j] = pack2(h0a, h0b);
        al[j] = pack2(__float2half_rn(r[j].x - __half2float(h0a)),
                      __float2half_rn(r[j].y - __half2float(h0b)));
    }
}

// ---- main ----
__global__ __launch_bounds__(TPB, 2)
void routing_mma(const float* __restrict__ x,
                 const float* __restrict__ nz,
                 float* __restrict__ out)
{
    extern __shared__ uint4 sm4[];
    const int tid = threadIdx.x;
    const int wid = tid >> 5;
    const int lane = tid & 31;
    const int gid = lane >> 2;
    const int tig = lane & 3;
    const int r0 = blockIdx.x * BM;
    const int m0 = wid * 16;              // warp rows [m0, m0+16)

    float c[16][4];
    #pragma unroll
    for (int nt = 0; nt < 16; nt++)
        #pragma unroll
        for (int j = 0; j < 4; j++) c[nt][j] = 0.f;

    // A direct-gmem pointers for this lane's fragment rows
    const float* xr0 = x + (size_t)(r0 + m0 + gid) * KDIM + 2 * tig;
    const float* xr8 = x + (size_t)(r0 + m0 + gid + 8) * KDIM + 2 * tig;

    const uint32_t sb = smem_u32(sm4);

    uint32_t ah[2][4], al[2][4];      // current chunk fragments
    float2 raw[2][4];                 // prefetched next-chunk raw pairs

    // ---- prologue: chunk 0 ----
    {
        #pragma unroll
        for (int s = 0; s < 2; s++) {
            raw[s][0] = *(const float2*)(xr0 + s * 16);
            raw[s][1] = *(const float2*)(xr8 + s * 16);
            raw[s][2] = *(const float2*)(xr0 + s * 16 + 8);
            raw[s][3] = *(const float2*)(xr8 + s * 16 + 8);
        }
        const uint4* src = g_wb + tid;   // chunk 0 = k16 steps 0,1
        #pragma unroll
        for (int j = 0; j < 4; j++) {
            uint32_t dst = sb + (uint32_t)(j * 256 + tid) * 16u;
            CP_ASYNC16(dst, src + j * 256);
        }
        CP_COMMIT();
        cvt_frag(raw[0], ah[0], al[0]);
        cvt_frag(raw[1], ah[1], al[1]);
        CP_WAIT0();
    }
    __syncthreads();

    int p = 0;
    for (int t = 0; t < NCHUNK; t++) {
        const bool more = (t + 1 < NCHUNK);
        if (more) {
            const int k0 = (t + 1) * BKC;
            #pragma unroll
            for (int s = 0; s < 2; s++) {
                raw[s][0] = *(const float2*)(xr0 + k0 + s * 16);
                raw[s][1] = *(const float2*)(xr8 + k0 + s * 16);
                raw[s][2] = *(const float2*)(xr0 + k0 + s * 16 + 8);
                raw[s][3] = *(const float2*)(xr8 + k0 + s * 16 + 8);
            }
            const uint4* src = g_wb + (size_t)(t + 1) * 1024 + tid;
            const int qb = 1 - p;
            #pragma unroll
            for (int j = 0; j < 4; j++) {
                uint32_t dst = sb + (uint32_t)(qb * BUF_U + j * 256 + tid) * 16u;
                CP_ASYNC16(dst, src + j * 256);
            }
            CP_COMMIT();
        }

        // ---- compute chunk t: B from smem buffer p, A from registers ----
        {
            const uint4* buf = sm4 + p * BUF_U;
            #pragma unroll
            for (int s = 0; s < 2; s++) {
                const uint4* bb = buf + s * 512;
                #pragma unroll
                for (int nt = 0; nt < 16; nt++) {
                    uint4 Bv = bb[(nt * 8 + gid) * 4 + tig];
                    mma16(c[nt], ah[s][0], ah[s][1], ah[s][2], ah[s][3], Bv.x, Bv.y);
                    mma16(c[nt], ah[s][0], ah[s][1], ah[s][2], ah[s][3], Bv.z, Bv.w);
                    mma16(c[nt], al[s][0], al[s][1], al[s][2], al[s][3], Bv.x, Bv.y);
                }
            }
        }

        if (more) {
            cvt_frag(raw[0], ah[0], al[0]);
            cvt_frag(raw[1], ah[1], al[1]);
            CP_WAIT0();
            __syncthreads();
            p = 1 - p;
        }
    }

    // ---- epilogue: rows rA = r0+m0+gid, rB = rA+8; intra-quad top-2 ----
    const float S = 1.0f / 256.0f;   // undo weight pre-scale (exact)
    const int rA = r0 + m0 + gid;
    const int rB = rA + 8;
    float v1[2] = {-INFINITY, -INFINITY}, v2[2] = {-INFINITY, -INFINITY};
    int   i1[2] = {0x7fffffff, 0x7fffffff}, i2[2] = {0x7fffffff, 0x7fffffff};

    #pragma unroll
    for (int nt = 0; nt < 8; nt++) {
        const int e0 = nt * 8 + 2 * tig;
        float2 za = *(const float2*)(nz + (size_t)rA * EDIM + e0);
        float2 zb = *(const float2*)(nz + (size_t)rB * EDIM + e0);
        const float zz[2][2] = {{za.x, za.y}, {zb.x, zb.y}};
        #pragma unroll
        for (int hh = 0; hh < 2; hh++) {
            #pragma unroll
            for (int j = 0; j < 2; j++) {
                float g = c[nt][hh * 2 + j] * S;
                float s = c[nt + 8][hh * 2 + j] * S;
                float sp = fmaxf(s, 0.f) + log1pf(expf(-fabsf(s)));
                float v = fmaf(zz[hh][j], sp + 0.01f, g);
                const int e = e0 + j;
                if (v > v1[hh])      { v2[hh] = v1[hh]; i2[hh] = i1[hh]; v1[hh] = v; i1[hh] = e; }
                else if (v > v2[hh]) { v2[hh] = v; i2[hh] = e; }
            }
        }
    }

    #pragma unroll
    for (int hh = 0; hh < 2; hh++) {
        #pragma unroll
        for (int off = 1; off < 4; off <<= 1) {
            float ov1 = __shfl_xor_sync(0xffffffffu, v1[hh], off);
            int   oi1 = __shfl_xor_sync(0xffffffffu, i1[hh], off);
            float ov2 = __shfl_xor_sync(0xffffffffu, v2[hh], off);
            int   oi2 = __shfl_xor_sync(0xffffffffu, i2[hh], off);
            bool firstMine = (v1[hh] > ov1) || (v1[hh] == ov1 && i1[hh] < oi1);
            float nv1, nv2; int ni1, ni2;
            if (firstMine) {
                nv1 = v1[hh]; ni1 = i1[hh];
                bool s2 = (v2[hh] > ov1) || (v2[hh] == ov1 && i2[hh] < oi1);
                nv2 = s2 ? v2[hh] : ov1; ni2 = s2 ? i2[hh] : oi1;
            } else {
                nv1 = ov1; ni1 = oi1;
                bool s2 = (ov2 > v1[hh]) || (ov2 == v1[hh] && oi2 < i1[hh]);
                nv2 = s2 ? ov2 : v1[hh]; ni2 = s2 ? oi2 : i1[hh];
            }
            v1[hh] = nv1; i1[hh] = ni1; v2[hh] = nv2; i2[hh] = ni2;
        }
    }

    #pragma unroll
    for (int hh = 0; hh < 2; hh++) {
        float e2 = expf(v2[hh] - v1[hh]);
        float denom = 1.f + e2;
        float g1 = 1.f / denom;
        float g2 = e2 / denom;
        const int row = hh ? rB : rA;
        #pragma unroll
        for (int nt = 0; nt < 8; nt++) {
            const int e0 = nt * 8 + 2 * tig;
            float2 o;
            o.x = (e0 == i1[hh]) ? g1 : ((e0 == i2[hh]) ? g2 : 0.f);
            o.y = (e0 + 1 == i1[hh]) ? g1 : ((e0 + 1 == i2[hh]) ? g2 : 0.f);
            *(float2*)(out + (size_t)row * EDIM + e0) = o;
        }
    }
}

extern "C" void kernel_launch(void* const* d_in, const int* in_sizes, int n_in,
                              void* d_out, int out_size)
{
    const float* x  = (const float*)d_in[0];   // [32768, 2048]
    const float* wg = (const float*)d_in[1];   // [2048, 64]
    const float* wn = (const float*)d_in[2];   // [2048, 64]
    const float* nz = (const float*)d_in[3];   // [32768, 64]
    float* out = (float*)d_out;                // [32768, 64]

    prep_w<<<256, 256>>>(wg, wn);

    cudaFuncSetAttribute(routing_mma, cudaFuncAttributeMaxDynamicSharedMemorySize,
                         SMEM_BYTES);
    const int B = in_sizes[0] / KDIM;          // 32768
    routing_mma<<<B / BM, TPB, SMEM_BYTES>>>(x, nz, out);
}

// round 8
// speedup vs baseline: 1.5200x; 1.1802x over previous
#include <cuda_runtime.h>
#include <cuda_fp16.h>
#include <math.h>
#include <stdint.h>

// RoutingLayer via mma.sync m16n8k16 fp16 (portable PTX for sm_103 target).
// out[B,64] = scatter(softmax(top2(x@w_gate + noise*(softplus(x@w_noise)+0.01))))
// B=32768, D=2048, E=64. Fused GEMM N=128 (0..63 gate, 64..127 noise).
// FP16x2 split: x=h0+h1, (256*w)=h0+h1; h0h0 + h0h1 + h1h0, scaled 2^-8.
// R8: warp tile 32Mx128N, TPB=128 (4 warps) -> B smem re-read per CTA halves;
// A fragments direct from gmem; B double-buffered via cp.async. Grid 256, 2 CTA/SM.

#define KDIM 2048
#define EDIM 64
#define BM   128
#define BKC  32
#define NCHUNK (KDIM / BKC)   // 64
#define TPB  128

// smem: B only. Per buffer 1024 16B-units: unit = s*512 + n*4 + tig
#define BUF_U 1024
#define SMEM_BYTES (2 * BUF_U * 16)   // 32768

// pre-split weights: [k16 step s(128)][n(128)][tig(4)] uint4 = (b0_h0,b1_h0,b0_h1,b1_h1)
__device__ uint4 g_wb[128 * 128 * 4];   // 1 MB

__device__ __forceinline__ uint32_t pack2(__half lo, __half hi) {
    __half2 h = __halves2half2(lo, hi);
    return *(uint32_t*)&h;
}

__device__ __forceinline__ void mma16(float* c, uint32_t a0, uint32_t a1,
                                      uint32_t a2, uint32_t a3,
                                      uint32_t b0, uint32_t b1) {
    asm volatile(
        "mma.sync.aligned.m16n8k16.row.col.f32.f16.f16.f32 "
        "{%0,%1,%2,%3}, {%4,%5,%6,%7}, {%8,%9}, {%0,%1,%2,%3};"
        : "+f"(c[0]), "+f"(c[1]), "+f"(c[2]), "+f"(c[3])
        : "r"(a0), "r"(a1), "r"(a2), "r"(a3), "r"(b0), "r"(b1));
}

__device__ __forceinline__ uint32_t smem_u32(const void* p) {
    uint32_t a;
    asm("{ .reg .u64 t; cvta.to.shared.u64 t, %1; cvt.u32.u64 %0, t; }" : "=r"(a) : "l"(p));
    return a;
}
#define CP_ASYNC16(dst, src) \
    asm volatile("cp.async.cg.shared.global [%0], [%1], 16;" :: "r"(dst), "l"(src) : "memory")
#define CP_COMMIT() asm volatile("cp.async.commit_group;" ::: "memory")
#define CP_WAIT0()  asm volatile("cp.async.wait_group 0;" ::: "memory")

// ---- prep: split 256*w into fp16 (h0,h1), fragment-native B layout ----
__global__ void prep_w(const float* __restrict__ wg, const float* __restrict__ wn) {
    const int idx = blockIdx.x * blockDim.x + threadIdx.x;  // 0..65535
    const int tig = idx & 3;
    const int n   = (idx >> 2) & 127;
    const int s   = idx >> 9;            // k16 step 0..127
    const int kb  = s * 16;
    const int kk[4] = {kb + 2*tig, kb + 2*tig + 1, kb + 2*tig + 8, kb + 2*tig + 9};
    float v[4];
    #pragma unroll
    for (int j = 0; j < 4; j++)
        v[j] = 256.0f * ((n < 64) ? wg[kk[j] * 64 + n] : wn[kk[j] * 64 + (n - 64)]);
    __half h0[4], h1[4];
    #pragma unroll
    for (int j = 0; j < 4; j++) {
        h0[j] = __float2half_rn(v[j]);
        h1[j] = __float2half_rn(v[j] - __half2float(h0[j]));
    }
    uint4 w4;
    w4.x = pack2(h0[0], h0[1]);
    w4.y = pack2(h0[2], h0[3]);
    w4.z = pack2(h1[0], h1[1]);
    w4.w = pack2(h1[2], h1[3]);
    g_wb[(size_t)(s * 128 + n) * 4 + tig] = w4;
}

// convert 4 raw float2 k-pairs into one mma A fragment (hi + lo)
__device__ __forceinline__ void cvt4(const float2 r0, const float2 r1,
                                     const float2 r2, const float2 r3,
                                     uint32_t* ah, uint32_t* al) {
    const float2 rr[4] = {r0, r1, r2, r3};
    #pragma unroll
    for (int j = 0; j < 4; j++) {
        __half a = __float2half_rn(rr[j].x);
        __half b = __float2half_rn(rr[j].y);
        ah[j] = pack2(a, b);
        al[j] = pack2(__float2half_rn(rr[j].x - __half2float(a)),
                      __float2half_rn(rr[j].y - __half2float(b)));
    }
}

// ---- main ----
__global__ __launch_bounds__(TPB, 2)
void routing_mma(const float* __restrict__ x,
                 const float* __restrict__ nz,
                 float* __restrict__ out)
{
    extern __shared__ uint4 sm4[];
    const int tid = threadIdx.x;
    const int wid = tid >> 5;            // 0..3
    const int lane = tid & 31;
    const int gid = lane >> 2;
    const int tig = lane & 3;
    const int r0 = blockIdx.x * BM;
    const int m0 = wid * 32;             // warp rows [m0, m0+32)

    float c[2][16][4];
    #pragma unroll
    for (int mt = 0; mt < 2; mt++)
        #pragma unroll
        for (int nt = 0; nt < 16; nt++)
            #pragma unroll
            for (int j = 0; j < 4; j++) c[mt][nt][j] = 0.f;

    // A direct-gmem pointers for this lane's fragment rows
    const float* xr[4];
    #pragma unroll
    for (int rr = 0; rr < 4; rr++)
        xr[rr] = x + (size_t)(r0 + m0 + gid + 8 * rr) * KDIM + 2 * tig;

    const uint32_t sb = smem_u32(sm4);

    uint32_t ah[2][8], al[2][8];   // current chunk fragments (s half, mt0:0-3 mt1:4-7)
    float2 raw[2][8];              // prefetched next-chunk raw pairs

    // ---- prologue: chunk 0 ----
    {
        #pragma unroll
        for (int s = 0; s < 2; s++)
            #pragma unroll
            for (int rr = 0; rr < 4; rr++) {
                raw[s][rr]     = *(const float2*)(xr[rr] + s * 16);
                raw[s][rr + 4] = *(const float2*)(xr[rr] + s * 16 + 8);
            }
        const uint4* src = g_wb + tid;   // chunk 0 = k16 steps 0,1
        #pragma unroll
        for (int j = 0; j < 8; j++) {
            uint32_t dst = sb + (uint32_t)(j * 128 + tid) * 16u;
            CP_ASYNC16(dst, src + j * 128);
        }
        CP_COMMIT();
        #pragma unroll
        for (int s = 0; s < 2; s++) {
            cvt4(raw[s][0], raw[s][1], raw[s][4], raw[s][5], &ah[s][0], &al[s][0]);
            cvt4(raw[s][2], raw[s][3], raw[s][6], raw[s][7], &ah[s][4], &al[s][4]);
        }
        CP_WAIT0();
    }
    __syncthreads();

    int p = 0;
    for (int t = 0; t < NCHUNK; t++) {
        const bool more = (t + 1 < NCHUNK);
        if (more) {
            const int k0 = (t + 1) * BKC;
            #pragma unroll
            for (int s = 0; s < 2; s++)
                #pragma unroll
                for (int rr = 0; rr < 4; rr++) {
                    raw[s][rr]     = *(const float2*)(xr[rr] + k0 + s * 16);
                    raw[s][rr + 4] = *(const float2*)(xr[rr] + k0 + s * 16 + 8);
                }
            const uint4* src = g_wb + (size_t)(t + 1) * 1024 + tid;
            const int qb = 1 - p;
            #pragma unroll
            for (int j = 0; j < 8; j++) {
                uint32_t dst = sb + (uint32_t)(qb * BUF_U + j * 128 + tid) * 16u;
                CP_ASYNC16(dst, src + j * 128);
            }
            CP_COMMIT();
        }

        // ---- compute chunk t: B from smem buffer p, A from registers ----
        {
            const uint4* buf = sm4 + p * BUF_U;
            #pragma unroll
            for (int s = 0; s < 2; s++) {
                const uint4* bb = buf + s * 512;
                const uint32_t* h0 = ah[s];
                const uint32_t* l0 = al[s];
                #pragma unroll
                for (int nt = 0; nt < 16; nt++) {
                    uint4 Bv = bb[(nt * 8 + gid) * 4 + tig];
                    // dep distance 2 via mt interleave; per-acc order h0h0,h0h1,h1h0
                    mma16(c[0][nt], h0[0], h0[1], h0[2], h0[3], Bv.x, Bv.y);
                    mma16(c[1][nt], h0[4], h0[5], h0[6], h0[7], Bv.x, Bv.y);
                    mma16(c[0][nt], h0[0], h0[1], h0[2], h0[3], Bv.z, Bv.w);
                    mma16(c[1][nt], h0[4], h0[5], h0[6], h0[7], Bv.z, Bv.w);
                    mma16(c[0][nt], l0[0], l0[1], l0[2], l0[3], Bv.x, Bv.y);
                    mma16(c[1][nt], l0[4], l0[5], l0[6], l0[7], Bv.x, Bv.y);
                }
            }
        }

        if (more) {
            #pragma unroll
            for (int s = 0; s < 2; s++) {
                cvt4(raw[s][0], raw[s][1], raw[s][4], raw[s][5], &ah[s][0], &al[s][0]);
                cvt4(raw[s][2], raw[s][3], raw[s][6], raw[s][7], &ah[s][4], &al[s][4]);
            }
            CP_WAIT0();
            __syncthreads();
            p = 1 - p;
        }
    }

    // ---- epilogue: 4 rows per lane (gid+8*hh), intra-quad top-2 ----
    const float S = 1.0f / 256.0f;   // undo weight pre-scale (exact)
    float v1[4] = {-INFINITY, -INFINITY, -INFINITY, -INFINITY};
    float v2[4] = {-INFINITY, -INFINITY, -INFINITY, -INFINITY};
    int   i1[4] = {0x7fffffff, 0x7fffffff, 0x7fffffff, 0x7fffffff};
    int   i2[4] = {0x7fffffff, 0x7fffffff, 0x7fffffff, 0x7fffffff};

    #pragma unroll
    for (int hh = 0; hh < 4; hh++) {
        const int row = r0 + m0 + gid + 8 * hh;
        const int mt = hh >> 1;
        const int jb = (hh & 1) * 2;
        #pragma unroll
        for (int nt = 0; nt < 8; nt++) {
            const int e0 = nt * 8 + 2 * tig;
            float2 z = *(const float2*)(nz + (size_t)row * EDIM + e0);
            const float zf[2] = {z.x, z.y};
            #pragma unroll
            for (int j = 0; j < 2; j++) {
                float g = c[mt][nt][jb + j] * S;
                float s = c[mt][nt + 8][jb + j] * S;
                float sp = fmaxf(s, 0.f) + log1pf(expf(-fabsf(s)));
                float v = fmaf(zf[j], sp + 0.01f, g);
                const int e = e0 + j;
                if (v > v1[hh])      { v2[hh] = v1[hh]; i2[hh] = i1[hh]; v1[hh] = v; i1[hh] = e; }
                else if (v > v2[hh]) { v2[hh] = v; i2[hh] = e; }
            }
        }
    }

    #pragma unroll
    for (int hh = 0; hh < 4; hh++) {
        #pragma unroll
        for (int off = 1; off < 4; off <<= 1) {
            float ov1 = __shfl_xor_sync(0xffffffffu, v1[hh], off);
            int   oi1 = __shfl_xor_sync(0xffffffffu, i1[hh], off);
            float ov2 = __shfl_xor_sync(0xffffffffu, v2[hh], off);
            int   oi2 = __shfl_xor_sync(0xffffffffu, i2[hh], off);
            bool firstMine = (v1[hh] > ov1) || (v1[hh] == ov1 && i1[hh] < oi1);
            float nv1, nv2; int ni1, ni2;
            if (firstMine) {
                nv1 = v1[hh]; ni1 = i1[hh];
                bool s2 = (v2[hh] > ov1) || (v2[hh] == ov1 && i2[hh] < oi1);
                nv2 = s2 ? v2[hh] : ov1; ni2 = s2 ? i2[hh] : oi1;
            } else {
                nv1 = ov1; ni1 = oi1;
                bool s2 = (ov2 > v1[hh]) || (ov2 == v1[hh] && oi2 < i1[hh]);
                nv2 = s2 ? ov2 : v1[hh]; ni2 = s2 ? oi2 : i1[hh];
            }
            v1[hh] = nv1; i1[hh] = ni1; v2[hh] = nv2; i2[hh] = ni2;
        }
    }

    #pragma unroll
    for (int hh = 0; hh < 4; hh++) {
        float e2 = expf(v2[hh] - v1[hh]);
        float denom = 1.f + e2;
        float g1 = 1.f / denom;
        float g2 = e2 / denom;
        const int row = r0 + m0 + gid + 8 * hh;
        #pragma unroll
        for (int nt = 0; nt < 8; nt++) {
            const int e0 = nt * 8 + 2 * tig;
            float2 o;
            o.x = (e0 == i1[hh]) ? g1 : ((e0 == i2[hh]) ? g2 : 0.f);
            o.y = (e0 + 1 == i1[hh]) ? g1 : ((e0 + 1 == i2[hh]) ? g2 : 0.f);
            *(float2*)(out + (size_t)row * EDIM + e0) = o;
        }
    }
}

extern "C" void kernel_launch(void* const* d_in, const int* in_sizes, int n_in,
                              void* d_out, int out_size)
{
    const float* x  = (const float*)d_in[0];   // [32768, 2048]
    const float* wg = (const float*)d_in[1];   // [2048, 64]
    const float* wn = (const float*)d_in[2];   // [2048, 64]
    const float* nz = (const float*)d_in[3];   // [32768, 64]
    float* out = (float*)d_out;                // [32768, 64]

    prep_w<<<256, 256>>>(wg, wn);

    cudaFuncSetAttribute(routing_mma, cudaFuncAttributeMaxDynamicSharedMemorySize,
                         SMEM_BYTES);
    const int B = in_sizes[0] / KDIM;          // 32768
    routing_mma<<<B / BM, TPB, SMEM_BYTES>>>(x, nz, out);
}